// round 15
// baseline (speedup 1.0000x reference)
#include <cuda_runtime.h>
#include <cuda_fp16.h>
#include <cstdint>

#define N_NODES 50000
#define N_EDGES 800000
#define F 64
#define TILE_M 128
#define ROW_STRIDE 132      // f32 stride of staged rows
#define WS_STRIDE 72        // float2 stride of W hi/lo in smem
#define SCAN_BLOCKS 196

// Scratch (allocation-free: __device__ globals)
__device__ int    g_deg[N_NODES];        // invariant: zero on entry (scan23 restores)
__device__ int    g_off[N_NODES + 1];
__device__ int    g_cur[N_NODES];
__device__ int    g_csr[N_EDGES];
__device__ int    g_bsum[SCAN_BLOCKS];
__device__ float  g_h[N_NODES * F];
__device__ float  g_agg[N_NODES * F];
__device__ __half g_half[N_NODES * F];   // fp16 mirror of gather source
__device__ float2 g_ws1[128 * 64];       // W1 hi/lo split (3xTF32)
__device__ float2 g_ws2[128 * 64];       // W2 hi/lo split

// Per-warp dtype detect: 1 cached 8B load/lane + ballot.
__device__ __forceinline__ int warp_detect_is64(const void* ei) {
    int lane = threadIdx.x & 31;
    long long v = ((const long long*)ei)[lane & 15];
    unsigned m = __ballot_sync(0xffffffffu, v >= 0 && v < N_NODES);
    return m == 0xffffffffu;
}

__device__ __forceinline__ int load_idx(const void* ei, int i, int is64) {
    if (is64) return (int)((const long long*)ei)[i];
    return ((const int*)ei)[i];
}

__device__ __forceinline__ unsigned tf32_hi(float a) {
    unsigned r;
    asm("cvt.rna.tf32.f32 %0, %1;" : "=r"(r) : "f"(a));
    return r;
}

// ---------------------------------------------------------------------------
// Stream B: x -> fp16 mirror + W1/W2 hi/lo split.
// ---------------------------------------------------------------------------
__global__ void convert_kernel(const float* __restrict__ x,
                               const float* __restrict__ W1,
                               const float* __restrict__ W2) {
    int i = blockIdx.x * blockDim.x + threadIdx.x;
    if (i < N_NODES * F / 2) {
        float2 xv = ((const float2*)x)[i];
        ((__half2*)g_half)[i] = __floats2half2_rn(xv.x, xv.y);
    }
    if (i < 2 * 128 * 64) {
        const float* Wsel = (i < 128 * 64) ? W1 : W2;
        float2* dst = (i < 128 * 64) ? g_ws1 : g_ws2;
        int idx = i & (128 * 64 - 1);
        float w = Wsel[idx];
        unsigned hb = tf32_hi(w);
        float hf = __uint_as_float(hb);
        unsigned lb = tf32_hi(w - hf);
        dst[idx] = make_float2(hf, __uint_as_float(lb));
    }
}

// ---------------------------------------------------------------------------
// CSR build: hist -> scan1 -> scan23 -> fill
// ---------------------------------------------------------------------------
__global__ void hist_kernel(const void* __restrict__ ei) {
    int is64 = warp_detect_is64(ei);
    int e = blockIdx.x * blockDim.x + threadIdx.x;
    if (e >= N_EDGES) return;
    int d = load_idx(ei, N_EDGES + e, is64);
    if ((unsigned)d < N_NODES) atomicAdd(&g_deg[d], 1);
}

__global__ void scan1_kernel() {
    __shared__ int sh[256];
    int t = threadIdx.x;
    int i = blockIdx.x * 256 + t;
    int v = (i < N_NODES) ? g_deg[i] : 0;
    sh[t] = v;
    __syncthreads();
    #pragma unroll
    for (int ofs = 1; ofs < 256; ofs <<= 1) {
        int add = (t >= ofs) ? sh[t - ofs] : 0;
        __syncthreads();
        sh[t] += add;
        __syncthreads();
    }
    if (i < N_NODES) g_off[i + 1] = sh[t];
    if (t == 255) g_bsum[blockIdx.x] = sh[255];
}

__global__ void scan23_kernel() {
    __shared__ int sh[256];
    int t = threadIdx.x;
    sh[t] = (t < SCAN_BLOCKS) ? g_bsum[t] : 0;
    __syncthreads();
    #pragma unroll
    for (int ofs = 1; ofs < 256; ofs <<= 1) {
        int add = (t >= ofs) ? sh[t - ofs] : 0;
        __syncthreads();
        sh[t] += add;
        __syncthreads();
    }
    int prefix = (blockIdx.x > 0) ? sh[blockIdx.x - 1] : 0;
    int i = blockIdx.x * 256 + t;
    if (i < N_NODES) {
        g_off[i + 1] += prefix;
        g_deg[i] = 0;     // restore hist invariant
        g_cur[i] = 0;     // fill precondition
    }
    if (i == 0) g_off[0] = 0;
}

__global__ void fill_kernel(const void* __restrict__ ei) {
    int is64 = warp_detect_is64(ei);
    int e = blockIdx.x * blockDim.x + threadIdx.x;
    if (e >= N_EDGES) return;
    int s = load_idx(ei, e, is64);
    int d = load_idx(ei, N_EDGES + e, is64);
    if ((unsigned)s >= N_NODES || (unsigned)d >= N_NODES) return;
    int pos = atomicAdd(&g_cur[d], 1);
    g_csr[g_off[d] + pos] = s;
}

// ---------------------------------------------------------------------------
// CSR mean-aggregation from fp16 mirror -> g_agg (f32).
// One node per warp; 4 edge-slots x 8 lanes x uint4 (LDG.128).
// UNROLL-4 per slot -> up to 16 edges in flight per warp (MLP fix).
// ---------------------------------------------------------------------------
__device__ __forceinline__ void acc_u4(uint4 u, float2& a0, float2& a1,
                                       float2& a2, float2& a3) {
    float2 p;
    p = __half22float2(*(__half2*)&u.x); a0.x += p.x; a0.y += p.y;
    p = __half22float2(*(__half2*)&u.y); a1.x += p.x; a1.y += p.y;
    p = __half22float2(*(__half2*)&u.z); a2.x += p.x; a2.y += p.y;
    p = __half22float2(*(__half2*)&u.w); a3.x += p.x; a3.y += p.y;
}

__global__ void __launch_bounds__(256)
agg_kernel() {
    int warp = threadIdx.x >> 5, lane = threadIdx.x & 31;
    int n = blockIdx.x * 8 + warp;
    if (n >= N_NODES) return;
    int slot  = lane >> 3;
    int fpart = lane & 7;

    const uint4* xh4 = (const uint4*)g_half;

    int e0 = g_off[n], e1 = g_off[n + 1];
    float2 a0 = make_float2(0.f, 0.f), a1 = a0, a2 = a0, a3 = a0;

    int e = e0 + slot;
    // 4 independent gathers in flight per lane (16 edges per warp).
    for (; e + 12 < e1; e += 16) {
        int s0 = g_csr[e];
        int s1 = g_csr[e + 4];
        int s2 = g_csr[e + 8];
        int s3 = g_csr[e + 12];
        uint4 u0 = xh4[s0 * 8 + fpart];
        uint4 u1 = xh4[s1 * 8 + fpart];
        uint4 u2 = xh4[s2 * 8 + fpart];
        uint4 u3 = xh4[s3 * 8 + fpart];
        acc_u4(u0, a0, a1, a2, a3);
        acc_u4(u1, a0, a1, a2, a3);
        acc_u4(u2, a0, a1, a2, a3);
        acc_u4(u3, a0, a1, a2, a3);
    }
    for (; e < e1; e += 4) {
        int s0 = g_csr[e];
        uint4 u0 = xh4[s0 * 8 + fpart];
        acc_u4(u0, a0, a1, a2, a3);
    }

    #pragma unroll
    for (int m = 8; m <= 16; m <<= 1) {
        a0.x += __shfl_xor_sync(0xffffffffu, a0.x, m);
        a0.y += __shfl_xor_sync(0xffffffffu, a0.y, m);
        a1.x += __shfl_xor_sync(0xffffffffu, a1.x, m);
        a1.y += __shfl_xor_sync(0xffffffffu, a1.y, m);
        a2.x += __shfl_xor_sync(0xffffffffu, a2.x, m);
        a2.y += __shfl_xor_sync(0xffffffffu, a2.y, m);
        a3.x += __shfl_xor_sync(0xffffffffu, a3.x, m);
        a3.y += __shfl_xor_sync(0xffffffffu, a3.y, m);
    }

    if (slot == 0) {
        float inv = 1.0f / fmaxf((float)(e1 - e0), 1.0f);
        float4* dst = (float4*)(g_agg + n * 64 + fpart * 8);
        dst[0] = make_float4(a0.x * inv, a0.y * inv, a1.x * inv, a1.y * inv);
        dst[1] = make_float4(a2.x * inv, a2.y * inv, a3.x * inv, a3.y * inv);
    }
}

// ---------------------------------------------------------------------------
// Tensor-core GEMM (3xTF32): out = [x || agg] @ W + b (+ReLU)
// ---------------------------------------------------------------------------
__device__ __forceinline__ void mma_tf32(float* c, unsigned a0, unsigned a1,
                                         unsigned a2, unsigned a3,
                                         unsigned b0, unsigned b1) {
    asm volatile(
        "mma.sync.aligned.m16n8k8.row.col.f32.tf32.tf32.f32 "
        "{%0,%1,%2,%3}, {%4,%5,%6,%7}, {%8,%9}, {%0,%1,%2,%3};"
        : "+f"(c[0]), "+f"(c[1]), "+f"(c[2]), "+f"(c[3])
        : "r"(a0), "r"(a1), "r"(a2), "r"(a3), "r"(b0), "r"(b1));
}

__global__ void __launch_bounds__(256)
gemm_kernel(const float* __restrict__ xin, const float2* __restrict__ Wsplit,
            const float* __restrict__ bias, float* __restrict__ out,
            int relu, int to_half) {
    extern __shared__ float sm[];
    float*  row = sm;
    float2* Ws2 = (float2*)(sm + TILE_M * ROW_STRIDE);

    int tid = threadIdx.x;

    const float4* wsrc = (const float4*)Wsplit;
    #pragma unroll
    for (int i = 0; i < 16; i++) {
        int j = tid + i * 256;
        int f2 = j * 2;
        int k = f2 >> 6, c = f2 & 63;
        *(float4*)&Ws2[k * WS_STRIDE + c] = wsrc[j];
    }

    int base = blockIdx.x * TILE_M;
    #pragma unroll
    for (int i = 0; i < 8; i++) {
        int idx = tid + i * 256;
        int nl = idx >> 4, q = idx & 15;
        int n = base + nl;
        int nc = n < N_NODES ? n : N_NODES - 1;
        float4 xv = ((const float4*)xin)[nc * 16 + q];
        *(float4*)&row[nl * ROW_STRIDE + q * 4] = xv;
        float4 av = ((const float4*)g_agg)[nc * 16 + q];
        *(float4*)&row[nl * ROW_STRIDE + 64 + q * 4] = av;
    }
    __syncthreads();

    int warp = tid >> 5, lane = tid & 31;
    int g = lane >> 2, t = lane & 3;
    int r0 = warp * 16 + g;

    float acc[8][4];
    #pragma unroll
    for (int nt = 0; nt < 8; nt++) {
        float2 bv = ((const float2*)bias)[nt * 4 + t];
        acc[nt][0] = bv.x; acc[nt][1] = bv.y;
        acc[nt][2] = bv.x; acc[nt][3] = bv.y;
    }

    #pragma unroll 2
    for (int ks = 0; ks < 16; ks++) {
        int k0 = ks * 8;
        float a0f = row[r0 * ROW_STRIDE + k0 + t];
        float a1f = row[(r0 + 8) * ROW_STRIDE + k0 + t];
        float a2f = row[r0 * ROW_STRIDE + k0 + t + 4];
        float a3f = row[(r0 + 8) * ROW_STRIDE + k0 + t + 4];
        unsigned ah0 = tf32_hi(a0f), ah1 = tf32_hi(a1f);
        unsigned ah2 = tf32_hi(a2f), ah3 = tf32_hi(a3f);
        unsigned al0 = tf32_hi(a0f - __uint_as_float(ah0));
        unsigned al1 = tf32_hi(a1f - __uint_as_float(ah1));
        unsigned al2 = tf32_hi(a2f - __uint_as_float(ah2));
        unsigned al3 = tf32_hi(a3f - __uint_as_float(ah3));

        #pragma unroll
        for (int nt = 0; nt < 8; nt++) {
            float2 w0 = Ws2[(k0 + t)     * WS_STRIDE + nt * 8 + g];
            float2 w1 = Ws2[(k0 + t + 4) * WS_STRIDE + nt * 8 + g];
            unsigned bh0 = __float_as_uint(w0.x), bl0 = __float_as_uint(w0.y);
            unsigned bh1 = __float_as_uint(w1.x), bl1 = __float_as_uint(w1.y);
            mma_tf32(acc[nt], ah0, ah1, ah2, ah3, bh0, bh1);
            mma_tf32(acc[nt], ah0, ah1, ah2, ah3, bl0, bl1);
            mma_tf32(acc[nt], al0, al1, al2, al3, bh0, bh1);
        }
    }

    int n0 = base + r0;
    int n1 = n0 + 8;
    float2*  out2 = (float2*)out;
    __half2* oh2  = (__half2*)g_half;
    #pragma unroll
    for (int nt = 0; nt < 8; nt++) {
        float c0 = acc[nt][0], c1 = acc[nt][1];
        float c2 = acc[nt][2], c3 = acc[nt][3];
        if (relu) {
            c0 = fmaxf(c0, 0.f); c1 = fmaxf(c1, 0.f);
            c2 = fmaxf(c2, 0.f); c3 = fmaxf(c3, 0.f);
        }
        int colp = nt * 4 + t;
        if (n0 < N_NODES) {
            out2[n0 * 32 + colp] = make_float2(c0, c1);
            if (to_half) oh2[n0 * 32 + colp] = __floats2half2_rn(c0, c1);
        }
        if (n1 < N_NODES) {
            out2[n1 * 32 + colp] = make_float2(c2, c3);
            if (to_half) oh2[n1 * 32 + colp] = __floats2half2_rn(c2, c3);
        }
    }
}

// ---------------------------------------------------------------------------
extern "C" void kernel_launch(void* const* d_in, const int* in_sizes, int n_in,
                              void* d_out, int out_size) {
    const float* x   = (const float*)d_in[0];
    const void*  ei  = d_in[1];
    const float* W1  = (const float*)d_in[2];
    const float* b1  = (const float*)d_in[3];
    const float* W2  = (const float*)d_in[4];
    const float* b2  = (const float*)d_in[5];
    float*       out = (float*)d_out;

    float*  hbuf = nullptr;
    float2* ws1  = nullptr;
    float2* ws2  = nullptr;
    cudaGetSymbolAddress((void**)&hbuf, g_h);
    cudaGetSymbolAddress((void**)&ws1, g_ws1);
    cudaGetSymbolAddress((void**)&ws2, g_ws2);

    static cudaStream_t sB = nullptr;
    static cudaEvent_t evFork = nullptr, evJoin = nullptr;
    if (!sB) {
        cudaStreamCreateWithFlags(&sB, cudaStreamNonBlocking);
        cudaEventCreateWithFlags(&evFork, cudaEventDisableTiming);
        cudaEventCreateWithFlags(&evJoin, cudaEventDisableTiming);
    }

    const int CONV_BLOCKS = (N_NODES * F / 2 + 255) / 256;       // 6250
    const int EDGE_BLOCKS = (N_EDGES + 255) / 256;               // 3125
    const int AGG_BLOCKS  = (N_NODES + 7) / 8;                   // 6250
    const int GEMM_BLOCKS = (N_NODES + TILE_M - 1) / TILE_M;     // 391
    const int SMEM_BYTES  = (TILE_M * ROW_STRIDE) * 4 + 128 * WS_STRIDE * 8;

    cudaFuncSetAttribute(gemm_kernel,
                         cudaFuncAttributeMaxDynamicSharedMemorySize, SMEM_BYTES);

    cudaEventRecord(evFork, 0);
    cudaStreamWaitEvent(sB, evFork, 0);
    convert_kernel<<<CONV_BLOCKS, 256, 0, sB>>>(x, W1, W2);
    cudaEventRecord(evJoin, sB);

    hist_kernel<<<EDGE_BLOCKS, 256>>>(ei);
    scan1_kernel<<<SCAN_BLOCKS, 256>>>();
    scan23_kernel<<<SCAN_BLOCKS, 256>>>();
    fill_kernel<<<EDGE_BLOCKS, 256>>>(ei);

    cudaStreamWaitEvent(0, evJoin, 0);

    // Layer 1
    agg_kernel<<<AGG_BLOCKS, 256>>>();
    gemm_kernel<<<GEMM_BLOCKS, 256, SMEM_BYTES>>>(x, ws1, b1, hbuf,
                                                  /*relu=*/1, /*to_half=*/1);
    // Layer 2
    agg_kernel<<<AGG_BLOCKS, 256>>>();
    gemm_kernel<<<GEMM_BLOCKS, 256, SMEM_BYTES>>>(hbuf, ws2, b2, out,
                                                  /*relu=*/0, /*to_half=*/0);
}

// round 16
// speedup vs baseline: 1.0181x; 1.0181x over previous
#include <cuda_runtime.h>
#include <cuda_fp16.h>
#include <cstdint>

#define N_NODES 50000
#define N_EDGES 800000
#define F 64
#define TILE_M 128
#define ROW_STRIDE 132      // f32 stride of staged rows
#define WS_STRIDE 72        // float2 stride of W hi/lo in smem
#define SCAN_BLOCKS 196

// Scratch (allocation-free: __device__ globals)
__device__ int    g_deg[N_NODES];
__device__ int    g_off[N_NODES + 1];
__device__ int    g_cur[N_NODES];
__device__ int    g_csr[N_EDGES];
__device__ int    g_bsum[SCAN_BLOCKS];
__device__ float  g_h[N_NODES * F];
__device__ float  g_agg[N_NODES * F];
__device__ __half g_half[N_NODES * F];   // fp16 mirror of gather source
__device__ float2 g_ws1[128 * 64];       // W1 hi/lo split (3xTF32)
__device__ float2 g_ws2[128 * 64];       // W2 hi/lo split
__device__ int    g_is64;

__device__ __forceinline__ int load_idx(const void* ei, int i, int is64) {
    if (is64) return (int)((const long long*)ei)[i];
    return ((const int*)ei)[i];
}

__device__ __forceinline__ unsigned tf32_hi(float a) {
    unsigned r;
    asm("cvt.rna.tf32.f32 %0, %1;" : "=r"(r) : "f"(a));
    return r;
}

// ---------------------------------------------------------------------------
// Prep: dtype detect (thread 0) + zero degree + x->fp16 mirror + W split.
// ---------------------------------------------------------------------------
__global__ void prep_kernel(const void* __restrict__ ei,
                            const float* __restrict__ x,
                            const float* __restrict__ W1,
                            const float* __restrict__ W2) {
    int i = blockIdx.x * blockDim.x + threadIdx.x;
    if (i == 0) {
        const long long* p64 = (const long long*)ei;
        int ok = 1;
        #pragma unroll
        for (int j = 0; j < 16; j++) {
            long long v = p64[j];
            if (v < 0 || v >= N_NODES) ok = 0;
        }
        g_is64 = ok;
    }
    if (i < N_NODES) g_deg[i] = 0;
    if (i < N_NODES * F / 2) {
        float2 v = ((const float2*)x)[i];
        ((__half2*)g_half)[i] = __floats2half2_rn(v.x, v.y);
    }
    if (i < 2 * 128 * 64) {
        const float* Wsel = (i < 128 * 64) ? W1 : W2;
        float2* dst = (i < 128 * 64) ? g_ws1 : g_ws2;
        int idx = i & (128 * 64 - 1);
        float w = Wsel[idx];
        unsigned hb = tf32_hi(w);
        float hf = __uint_as_float(hb);
        unsigned lb = tf32_hi(w - hf);
        dst[idx] = make_float2(hf, __uint_as_float(lb));
    }
}

// ---------------------------------------------------------------------------
// CSR build: hist -> scan1 -> scan23 -> fill (proven)
// ---------------------------------------------------------------------------
__global__ void hist_kernel(const void* __restrict__ ei) {
    int e = blockIdx.x * blockDim.x + threadIdx.x;
    if (e >= N_EDGES) return;
    int d = load_idx(ei, N_EDGES + e, g_is64);
    if ((unsigned)d < N_NODES) atomicAdd(&g_deg[d], 1);
}

__global__ void scan1_kernel() {
    __shared__ int sh[256];
    int t = threadIdx.x;
    int i = blockIdx.x * 256 + t;
    int v = (i < N_NODES) ? g_deg[i] : 0;
    sh[t] = v;
    __syncthreads();
    #pragma unroll
    for (int ofs = 1; ofs < 256; ofs <<= 1) {
        int add = (t >= ofs) ? sh[t - ofs] : 0;
        __syncthreads();
        sh[t] += add;
        __syncthreads();
    }
    if (i < N_NODES) g_off[i + 1] = sh[t];
    if (t == 255) g_bsum[blockIdx.x] = sh[255];
}

__global__ void scan23_kernel() {
    __shared__ int sh[256];
    int t = threadIdx.x;
    sh[t] = (t < SCAN_BLOCKS) ? g_bsum[t] : 0;
    __syncthreads();
    #pragma unroll
    for (int ofs = 1; ofs < 256; ofs <<= 1) {
        int add = (t >= ofs) ? sh[t - ofs] : 0;
        __syncthreads();
        sh[t] += add;
        __syncthreads();
    }
    int prefix = (blockIdx.x > 0) ? sh[blockIdx.x - 1] : 0;
    int i = blockIdx.x * 256 + t;
    if (i < N_NODES) {
        g_off[i + 1] += prefix;
        g_cur[i] = 0;
    }
    if (i == 0) g_off[0] = 0;
}

__global__ void fill_kernel(const void* __restrict__ ei) {
    int e = blockIdx.x * blockDim.x + threadIdx.x;
    if (e >= N_EDGES) return;
    int is64 = g_is64;
    int s = load_idx(ei, e, is64);
    int d = load_idx(ei, N_EDGES + e, is64);
    if ((unsigned)s >= N_NODES || (unsigned)d >= N_NODES) return;
    int pos = atomicAdd(&g_cur[d], 1);
    g_csr[g_off[d] + pos] = s;
}

// ---------------------------------------------------------------------------
// CSR mean-aggregation: TWO nodes per warp (independent gather streams).
// 4 edge-slots x 8 lanes x uint4 per stream; fused main loop keeps
// 4 LDG.128 in flight per lane. Slot 0 stores node A, slot 1 stores node B.
// ---------------------------------------------------------------------------
__device__ __forceinline__ void acc_u4(uint4 u, float2& a0, float2& a1,
                                       float2& a2, float2& a3) {
    float2 p;
    p = __half22float2(*(__half2*)&u.x); a0.x += p.x; a0.y += p.y;
    p = __half22float2(*(__half2*)&u.y); a1.x += p.x; a1.y += p.y;
    p = __half22float2(*(__half2*)&u.z); a2.x += p.x; a2.y += p.y;
    p = __half22float2(*(__half2*)&u.w); a3.x += p.x; a3.y += p.y;
}

__global__ void __launch_bounds__(256)
agg_kernel() {
    int warp = threadIdx.x >> 5, lane = threadIdx.x & 31;
    int nA = blockIdx.x * 16 + warp * 2;
    if (nA >= N_NODES) return;
    int nB = nA + 1;
    bool hasB = (nB < N_NODES);
    int slot  = lane >> 3;
    int fpart = lane & 7;

    const uint4* xh4 = (const uint4*)g_half;

    int offA0 = g_off[nA], offA1 = g_off[nA + 1];
    int offB1 = hasB ? g_off[nB + 1] : offA1;

    float2 A0 = make_float2(0.f, 0.f), A1 = A0, A2 = A0, A3 = A0;
    float2 B0 = A0, B1 = A0, B2 = A0, B3 = A0;

    int eA = offA0 + slot, eAend = offA1;
    int eB = offA1 + slot, eBend = offB1;

    // Fused main loop: 2 gathers per stream in flight (4 per lane total).
    while (eA + 4 < eAend && eB + 4 < eBend) {
        int sA0 = g_csr[eA],     sA1 = g_csr[eA + 4];
        int sB0 = g_csr[eB],     sB1 = g_csr[eB + 4];
        uint4 uA0 = xh4[sA0 * 8 + fpart];
        uint4 uA1 = xh4[sA1 * 8 + fpart];
        uint4 uB0 = xh4[sB0 * 8 + fpart];
        uint4 uB1 = xh4[sB1 * 8 + fpart];
        acc_u4(uA0, A0, A1, A2, A3);
        acc_u4(uA1, A0, A1, A2, A3);
        acc_u4(uB0, B0, B1, B2, B3);
        acc_u4(uB1, B0, B1, B2, B3);
        eA += 8; eB += 8;
    }
    // Drain A (unroll-2 then single)
    for (; eA + 4 < eAend; eA += 8) {
        int s0 = g_csr[eA], s1 = g_csr[eA + 4];
        uint4 u0 = xh4[s0 * 8 + fpart];
        uint4 u1 = xh4[s1 * 8 + fpart];
        acc_u4(u0, A0, A1, A2, A3);
        acc_u4(u1, A0, A1, A2, A3);
    }
    for (; eA < eAend; eA += 4) {
        uint4 u0 = xh4[g_csr[eA] * 8 + fpart];
        acc_u4(u0, A0, A1, A2, A3);
    }
    // Drain B
    for (; eB + 4 < eBend; eB += 8) {
        int s0 = g_csr[eB], s1 = g_csr[eB + 4];
        uint4 u0 = xh4[s0 * 8 + fpart];
        uint4 u1 = xh4[s1 * 8 + fpart];
        acc_u4(u0, B0, B1, B2, B3);
        acc_u4(u1, B0, B1, B2, B3);
    }
    for (; eB < eBend; eB += 4) {
        uint4 u0 = xh4[g_csr[eB] * 8 + fpart];
        acc_u4(u0, B0, B1, B2, B3);
    }

    // Slot reduction (lane bits 3, 4) for both streams.
    #pragma unroll
    for (int m = 8; m <= 16; m <<= 1) {
        A0.x += __shfl_xor_sync(0xffffffffu, A0.x, m);
        A0.y += __shfl_xor_sync(0xffffffffu, A0.y, m);
        A1.x += __shfl_xor_sync(0xffffffffu, A1.x, m);
        A1.y += __shfl_xor_sync(0xffffffffu, A1.y, m);
        A2.x += __shfl_xor_sync(0xffffffffu, A2.x, m);
        A2.y += __shfl_xor_sync(0xffffffffu, A2.y, m);
        A3.x += __shfl_xor_sync(0xffffffffu, A3.x, m);
        A3.y += __shfl_xor_sync(0xffffffffu, A3.y, m);
        B0.x += __shfl_xor_sync(0xffffffffu, B0.x, m);
        B0.y += __shfl_xor_sync(0xffffffffu, B0.y, m);
        B1.x += __shfl_xor_sync(0xffffffffu, B1.x, m);
        B1.y += __shfl_xor_sync(0xffffffffu, B1.y, m);
        B2.x += __shfl_xor_sync(0xffffffffu, B2.x, m);
        B2.y += __shfl_xor_sync(0xffffffffu, B2.y, m);
        B3.x += __shfl_xor_sync(0xffffffffu, B3.x, m);
        B3.y += __shfl_xor_sync(0xffffffffu, B3.y, m);
    }

    if (slot == 0) {
        float inv = 1.0f / fmaxf((float)(offA1 - offA0), 1.0f);
        float4* dst = (float4*)(g_agg + nA * 64 + fpart * 8);
        dst[0] = make_float4(A0.x * inv, A0.y * inv, A1.x * inv, A1.y * inv);
        dst[1] = make_float4(A2.x * inv, A2.y * inv, A3.x * inv, A3.y * inv);
    } else if (slot == 1 && hasB) {
        float inv = 1.0f / fmaxf((float)(offB1 - offA1), 1.0f);
        float4* dst = (float4*)(g_agg + nB * 64 + fpart * 8);
        dst[0] = make_float4(B0.x * inv, B0.y * inv, B1.x * inv, B1.y * inv);
        dst[1] = make_float4(B2.x * inv, B2.y * inv, B3.x * inv, B3.y * inv);
    }
}

// ---------------------------------------------------------------------------
// Tensor-core GEMM (3xTF32): out = [x || agg] @ W + b (+ReLU)  (proven)
// ---------------------------------------------------------------------------
__device__ __forceinline__ void mma_tf32(float* c, unsigned a0, unsigned a1,
                                         unsigned a2, unsigned a3,
                                         unsigned b0, unsigned b1) {
    asm volatile(
        "mma.sync.aligned.m16n8k8.row.col.f32.tf32.tf32.f32 "
        "{%0,%1,%2,%3}, {%4,%5,%6,%7}, {%8,%9}, {%0,%1,%2,%3};"
        : "+f"(c[0]), "+f"(c[1]), "+f"(c[2]), "+f"(c[3])
        : "r"(a0), "r"(a1), "r"(a2), "r"(a3), "r"(b0), "r"(b1));
}

__global__ void __launch_bounds__(256)
gemm_kernel(const float* __restrict__ xin, const float2* __restrict__ Wsplit,
            const float* __restrict__ bias, float* __restrict__ out,
            int relu, int to_half) {
    extern __shared__ float sm[];
    float*  row = sm;
    float2* Ws2 = (float2*)(sm + TILE_M * ROW_STRIDE);

    int tid = threadIdx.x;

    const float4* wsrc = (const float4*)Wsplit;
    #pragma unroll
    for (int i = 0; i < 16; i++) {
        int j = tid + i * 256;
        int f2 = j * 2;
        int k = f2 >> 6, c = f2 & 63;
        *(float4*)&Ws2[k * WS_STRIDE + c] = wsrc[j];
    }

    int base = blockIdx.x * TILE_M;
    #pragma unroll
    for (int i = 0; i < 8; i++) {
        int idx = tid + i * 256;
        int nl = idx >> 4, q = idx & 15;
        int n = base + nl;
        int nc = n < N_NODES ? n : N_NODES - 1;
        float4 xv = ((const float4*)xin)[nc * 16 + q];
        *(float4*)&row[nl * ROW_STRIDE + q * 4] = xv;
        float4 av = ((const float4*)g_agg)[nc * 16 + q];
        *(float4*)&row[nl * ROW_STRIDE + 64 + q * 4] = av;
    }
    __syncthreads();

    int warp = tid >> 5, lane = tid & 31;
    int g = lane >> 2, t = lane & 3;
    int r0 = warp * 16 + g;

    float acc[8][4];
    #pragma unroll
    for (int nt = 0; nt < 8; nt++) {
        float2 bv = ((const float2*)bias)[nt * 4 + t];
        acc[nt][0] = bv.x; acc[nt][1] = bv.y;
        acc[nt][2] = bv.x; acc[nt][3] = bv.y;
    }

    #pragma unroll 2
    for (int ks = 0; ks < 16; ks++) {
        int k0 = ks * 8;
        float a0f = row[r0 * ROW_STRIDE + k0 + t];
        float a1f = row[(r0 + 8) * ROW_STRIDE + k0 + t];
        float a2f = row[r0 * ROW_STRIDE + k0 + t + 4];
        float a3f = row[(r0 + 8) * ROW_STRIDE + k0 + t + 4];
        unsigned ah0 = tf32_hi(a0f), ah1 = tf32_hi(a1f);
        unsigned ah2 = tf32_hi(a2f), ah3 = tf32_hi(a3f);
        unsigned al0 = tf32_hi(a0f - __uint_as_float(ah0));
        unsigned al1 = tf32_hi(a1f - __uint_as_float(ah1));
        unsigned al2 = tf32_hi(a2f - __uint_as_float(ah2));
        unsigned al3 = tf32_hi(a3f - __uint_as_float(ah3));

        #pragma unroll
        for (int nt = 0; nt < 8; nt++) {
            float2 w0 = Ws2[(k0 + t)     * WS_STRIDE + nt * 8 + g];
            float2 w1 = Ws2[(k0 + t + 4) * WS_STRIDE + nt * 8 + g];
            unsigned bh0 = __float_as_uint(w0.x), bl0 = __float_as_uint(w0.y);
            unsigned bh1 = __float_as_uint(w1.x), bl1 = __float_as_uint(w1.y);
            mma_tf32(acc[nt], ah0, ah1, ah2, ah3, bh0, bh1);
            mma_tf32(acc[nt], ah0, ah1, ah2, ah3, bl0, bl1);
            mma_tf32(acc[nt], al0, al1, al2, al3, bh0, bh1);
        }
    }

    int n0 = base + r0;
    int n1 = n0 + 8;
    float2*  out2 = (float2*)out;
    __half2* oh2  = (__half2*)g_half;
    #pragma unroll
    for (int nt = 0; nt < 8; nt++) {
        float c0 = acc[nt][0], c1 = acc[nt][1];
        float c2 = acc[nt][2], c3 = acc[nt][3];
        if (relu) {
            c0 = fmaxf(c0, 0.f); c1 = fmaxf(c1, 0.f);
            c2 = fmaxf(c2, 0.f); c3 = fmaxf(c3, 0.f);
        }
        int colp = nt * 4 + t;
        if (n0 < N_NODES) {
            out2[n0 * 32 + colp] = make_float2(c0, c1);
            if (to_half) oh2[n0 * 32 + colp] = __floats2half2_rn(c0, c1);
        }
        if (n1 < N_NODES) {
            out2[n1 * 32 + colp] = make_float2(c2, c3);
            if (to_half) oh2[n1 * 32 + colp] = __floats2half2_rn(c2, c3);
        }
    }
}

// ---------------------------------------------------------------------------
extern "C" void kernel_launch(void* const* d_in, const int* in_sizes, int n_in,
                              void* d_out, int out_size) {
    const float* x   = (const float*)d_in[0];
    const void*  ei  = d_in[1];
    const float* W1  = (const float*)d_in[2];
    const float* b1  = (const float*)d_in[3];
    const float* W2  = (const float*)d_in[4];
    const float* b2  = (const float*)d_in[5];
    float*       out = (float*)d_out;

    float*  hbuf = nullptr;
    float2* ws1  = nullptr;
    float2* ws2  = nullptr;
    cudaGetSymbolAddress((void**)&hbuf, g_h);
    cudaGetSymbolAddress((void**)&ws1, g_ws1);
    cudaGetSymbolAddress((void**)&ws2, g_ws2);

    const int PREP_BLOCKS = (N_NODES * F / 2 + 255) / 256;       // 6250
    const int EDGE_BLOCKS = (N_EDGES + 255) / 256;               // 3125
    const int AGG_BLOCKS  = (N_NODES + 15) / 16;                 // 3125
    const int GEMM_BLOCKS = (N_NODES + TILE_M - 1) / TILE_M;     // 391
    const int SMEM_BYTES  = (TILE_M * ROW_STRIDE) * 4 + 128 * WS_STRIDE * 8;

    cudaFuncSetAttribute(gemm_kernel,
                         cudaFuncAttributeMaxDynamicSharedMemorySize, SMEM_BYTES);

    prep_kernel<<<PREP_BLOCKS, 256>>>(ei, x, W1, W2);
    hist_kernel<<<EDGE_BLOCKS, 256>>>(ei);
    scan1_kernel<<<SCAN_BLOCKS, 256>>>();
    scan23_kernel<<<SCAN_BLOCKS, 256>>>();
    fill_kernel<<<EDGE_BLOCKS, 256>>>(ei);

    // Layer 1
    agg_kernel<<<AGG_BLOCKS, 256>>>();
    gemm_kernel<<<GEMM_BLOCKS, 256, SMEM_BYTES>>>(x, ws1, b1, hbuf,
                                                  /*relu=*/1, /*to_half=*/1);
    // Layer 2
    agg_kernel<<<AGG_BLOCKS, 256>>>();
    gemm_kernel<<<GEMM_BLOCKS, 256, SMEM_BYTES>>>(hbuf, ws2, b2, out,
                                                  /*relu=*/0, /*to_half=*/0);
}